// round 10
// baseline (speedup 1.0000x reference)
#include <cuda_runtime.h>
#include <cuda_fp16.h>
#include <cstdint>
#include <cstddef>

#define N_    128
#define CIN   8
#define HIN   128
#define WIN   128
#define COUT  64
#define OH    126
#define OW    126
#define G_    16
#define OPH   31
#define OPW   31

#define HB_   16
#define WB_   4
#define NTILES (N_ * HB_ * WB_)

// ---- smem layout (bytes) ----
// phase 1: sB2h [0,5120), sX [5120,18080)  (9 ic planes x 10 x 36, plane 8 zeros)
// phase 2: sO [0,38912)  (256 px x 38 floats), aliases phase-1
#define OFF_B2   0
#define OFF_X    5120
#define OFF_OUT  0
#define OFF_CB   38912
#define OFF_RED  39168
#define OFF_SG   41216
#define SMEM_TOTAL 41472

#define SO 38    // s_out px stride (19 f2, odd -> 2-way max on f2 stores = optimal)

// ---- device scratch ----
// B pairs: [oc(64)][kk(5)][r4(4)] uint2 = (half2(k0,k0+1), half2(k0+8,k0+9)), k0=16kk+2r4
__device__ uint2 g_B2h[64 * 20];
__device__ float g_sgn[64];
__device__ float g_ext[(size_t)N_ * COUT * OPH * OPW];
__device__ float g_ps[NTILES * G_];
__device__ float g_pq[NTILES * G_];
__device__ float g_mean[N_ * G_];
__device__ float g_rsig[N_ * G_];

__device__ __forceinline__ uint32_t pack_h2(float lo, float hi) {
    uint32_t r;
    asm("cvt.rn.f16x2.f32 %0, %1, %2;" : "=r"(r) : "f"(hi), "f"(lo));
    return r;
}

__device__ __forceinline__ void mma16(float* c, const uint32_t* a, uint32_t b0, uint32_t b1) {
    asm volatile(
        "mma.sync.aligned.m16n8k16.row.col.f32.f16.f16.f32 "
        "{%0,%1,%2,%3}, {%4,%5,%6,%7}, {%8,%9}, {%0,%1,%2,%3};"
        : "+f"(c[0]), "+f"(c[1]), "+f"(c[2]), "+f"(c[3])
        : "r"(a[0]), "r"(a[1]), "r"(a[2]), "r"(a[3]), "r"(b0), "r"(b1));
}

// k (< 80) -> sX offset ic*360 + kh*36 + kw   (sX layout [ic(9)][10][36])
__device__ __forceinline__ int koff(int k) {
    int ic = (k * 57) >> 9;
    int r  = k - 9 * ic;
    int kh = (r * 11) >> 5;
    int kw = r - 3 * kh;
    return ic * 360 + kh * 36 + kw;
}

// ---------------------------------------------------------------------------
// Kernel 0: weights -> fp16 pairs keyed [oc][kk][r4]; sign of a per oc.
// ---------------------------------------------------------------------------
__global__ void bprep_kernel(const float* __restrict__ cw,
                             const float* __restrict__ gnw,
                             const float* __restrict__ scale)
{
    int e = blockIdx.x * blockDim.x + threadIdx.x;
    if (e < 64) g_sgn[e] = (gnw[e] * scale[e] > 0.f) ? 1.f : -1.f;
    if (e >= 64 * 20) return;
    int oc = e / 20, rem = e - (e / 20) * 20;
    int kk = rem >> 2, r4 = rem & 3;
    int k0 = 16 * kk + 2 * r4;

    float w[4];
    #pragma unroll
    for (int i = 0; i < 4; ++i) {
        int k = k0 + ((i >> 1) << 3) + (i & 1);
        float v = 0.f;
        if (k < 72) {
            int ic = k / 9, r = k % 9;
            v = cw[((oc * 8 + ic) * 3 + r / 3) * 3 + (r % 3)];
        }
        w[i] = v;
    }
    __half2 p0 = __floats2half2_rn(w[0], w[1]);
    __half2 p1 = __floats2half2_rn(w[2], w[3]);
    uint2 out;
    out.x = *(uint32_t*)&p0;
    out.y = *(uint32_t*)&p1;
    g_B2h[e] = out;
}

// ---------------------------------------------------------------------------
// Kernel 1: implicit-GEMM conv (mma.sync fp16, f32 accum), 32-oc half per
// block, fused pool extreme + per-group partials. 256 threads.
// grid.x = WB_*2 (wb, half), grid.y = HB_, grid.z = N_.
// ---------------------------------------------------------------------------
__global__ __launch_bounds__(256, 3)
void conv_mma_kernel(const float* __restrict__ x, const float* __restrict__ cb)
{
    extern __shared__ char smem[];
    uint2*  sB2 = (uint2*)(smem + OFF_B2);    // [oc_l(32)][kk(5)][r4(4)]
    float*  sX  = (float*)(smem + OFF_X);     // [9][10][36]
    float*  sO  = (float*)(smem + OFF_OUT);   // [256][SO]
    float*  sCb = (float*)(smem + OFF_CB);
    float*  sRd = (float*)(smem + OFF_RED);
    float*  sSg = (float*)(smem + OFF_SG);

    const int tid  = threadIdx.x;
    const int wid  = tid >> 5;
    const int lane = tid & 31;
    const int wb   = blockIdx.x >> 1;
    const int half = blockIdx.x & 1;
    const int hb = blockIdx.y, n = blockIdx.z;
    const int h0 = hb * 8, w0 = wb * 32;
    const int ocb = half * 32;

    const int q  = lane >> 2;
    const int r4 = lane & 3;

    // copy this half's packed weights: 32 oc x 20 uint2 = 320 float4
    {
        const float4* src = (const float4*)(g_B2h + ocb * 20);
        float4* dst = (float4*)sB2;
        #pragma unroll 2
        for (int i = tid; i < 320; i += 256) dst[i] = src[i];
    }
    if (tid < 32) { sCb[tid] = cb[ocb + tid]; sSg[tid] = g_sgn[ocb + tid]; }

    // stage x: 9 ic-planes x 10 rows x 36 cols (plane 8 = zeros)
    for (int idx = tid; idx < 810; idx += 256) {
        int ic  = idx / 90, rem = idx - ic * 90;
        int hr  = rem / 9,  c4  = rem - hr * 9;
        int h = h0 + hr, gw = w0 + c4 * 4;
        float4 v = make_float4(0.f, 0.f, 0.f, 0.f);
        if (ic < CIN && h < HIN) {
            const float* rp = x + (((size_t)n * CIN + ic) * HIN + h) * WIN;
            if (gw + 3 < WIN) v = *(const float4*)(rp + gw);
            else {
                if (gw + 0 < WIN) v.x = rp[gw + 0];
                if (gw + 1 < WIN) v.y = rp[gw + 1];
                if (gw + 2 < WIN) v.z = rp[gw + 2];
            }
        }
        *(float4*)(sX + (ic * 10 + hr) * 36 + c4 * 4) = v;
    }
    __syncthreads();

    const int P = wid * 36 + 4 * q;

    float acc[2][4][4];
    #pragma unroll
    for (int t = 0; t < 2; ++t)
        #pragma unroll
        for (int j = 0; j < 4; ++j)
            #pragma unroll
            for (int u = 0; u < 4; ++u) acc[t][j][u] = 0.f;

    // ---- MMA mainloop: 5 k16-steps (K padded 72 -> 80), 4 n8-tiles ----
    #pragma unroll
    for (int kk = 0; kk < 5; ++kk) {
        const int k0 = 16 * kk + 2 * r4;
        const float* p00 = sX + koff(k0)     + P;
        const float* p01 = sX + koff(k0 + 1) + P;
        const float* p10 = sX + koff(k0 + 8) + P;
        const float* p11 = sX + koff(k0 + 9) + P;

        uint32_t a[2][4];
        #pragma unroll
        for (int t = 0; t < 2; ++t) {
            const int c = 2 * t;
            a[t][0] = pack_h2(p00[c],     p01[c]);
            a[t][1] = pack_h2(p00[c + 1], p01[c + 1]);
            a[t][2] = pack_h2(p10[c],     p11[c]);
            a[t][3] = pack_h2(p10[c + 1], p11[c + 1]);
        }
        const uint2* bp = sB2 + q * 20 + kk * 4 + r4;
        #pragma unroll
        for (int j = 0; j < 4; ++j) {
            uint2 bv = bp[j * 160];          // oc_l = 8j+q -> (8j)*20
            mma16(acc[0][j], a[0], bv.x, bv.y);
            mma16(acc[1][j], a[1], bv.x, bv.y);
        }
    }
    __syncthreads();   // sB2/sX dead; region becomes s_out

    // ---- epilogue: +bias, zero invalid, paired STS.64 -> sO[px][oc_l] ----
    const bool hok = (h0 + wid) < OH;
    #pragma unroll
    for (int t = 0; t < 2; ++t) {
        const int ww0 = 4 * q + 2 * t;
        const int px  = (wid << 5) + ww0;
        const bool v0 = hok && (w0 + ww0 < OW);
        const bool v1 = hok && (w0 + ww0 + 1 < OW);
        #pragma unroll
        for (int j = 0; j < 4; ++j) {
            const int oc = (j << 3) + (r4 << 1);
            float2 bc = *(float2*)(sCb + oc);
            float2 e0, e1;
            e0.x = v0 ? acc[t][j][0] + bc.x : 0.f;
            e0.y = v0 ? acc[t][j][1] + bc.y : 0.f;
            e1.x = v1 ? acc[t][j][2] + bc.x : 0.f;
            e1.y = v1 ? acc[t][j][3] + bc.y : 0.f;
            *(float2*)(sO + px * SO + oc)       = e0;
            *(float2*)(sO + (px + 1) * SO + oc) = e1;
        }
    }
    __syncthreads();

    // ---- stats: column scan, 8 partials per oc_l, fixed order ----
    {
        const int oc = tid & 31, part = tid >> 5;
        const float* p = sO + part * 32 * SO + oc;
        float s = 0.f, qq = 0.f;
        #pragma unroll 8
        for (int i = 0; i < 32; ++i) {
            float v = p[i * SO];
            s += v; qq = fmaf(v, v, qq);
        }
        sRd[tid] = s; sRd[256 + tid] = qq;
    }
    __syncthreads();

    const int tile = (n * HB_ + hb) * WB_ + wb;
    if (tid < 8) {
        float S = 0.f, Q = 0.f;
        #pragma unroll
        for (int part = 0; part < 8; ++part)
            #pragma unroll
            for (int c2 = 0; c2 < 4; ++c2) {
                S += sRd[part * 32 + tid * 4 + c2];
                Q += sRd[256 + part * 32 + tid * 4 + c2];
            }
        g_ps[tile * G_ + half * 8 + tid] = S;
        g_pq[tile * G_ + half * 8 + tid] = Q;
    }

    // ---- pool: 2 prow x 8 pcol x 32 oc = 512 tasks, 2/thread ----
    #pragma unroll
    for (int i = 0; i < 2; ++i) {
        const int task = tid + (i << 8);
        const int oc = task & 31, j = (task >> 5) & 7, prl = task >> 8;
        const int pw = wb * 8 + j, pr = hb * 2 + prl;
        if (pw < OPW && pr < OPH) {
            float mx = -3.4e38f, mn = 3.4e38f;
            #pragma unroll
            for (int a2 = 0; a2 < 4; ++a2)
                #pragma unroll
                for (int b2 = 0; b2 < 4; ++b2) {
                    float v = sO[((prl * 4 + a2) * 32 + j * 4 + b2) * SO + oc];
                    mx = fmaxf(mx, v); mn = fminf(mn, v);
                }
            size_t o = ((size_t)(n * COUT + ocb + oc) * OPH + pr) * OPW + pw;
            g_ext[o] = (sSg[oc] > 0.f) ? mx : mn;
        }
    }
}

// ---------------------------------------------------------------------------
// Kernel 2: reduce per-tile partials -> mean, rsig. One warp per (n,g),
// fixed shuffle tree (deterministic).
// ---------------------------------------------------------------------------
__global__ __launch_bounds__(256) void stats_reduce_kernel()
{
    const int wg   = (blockIdx.x * 256 + threadIdx.x) >> 5;   // (n,g) index
    const int lane = threadIdx.x & 31;
    if (wg >= N_ * G_) return;
    const int n = wg / G_, g = wg - n * G_;

    const int base = n * HB_ * WB_;   // 64 tiles per n
    float S = g_ps[(base + lane) * G_ + g] + g_ps[(base + 32 + lane) * G_ + g];
    float Q = g_pq[(base + lane) * G_ + g] + g_pq[(base + 32 + lane) * G_ + g];
    #pragma unroll
    for (int m = 16; m > 0; m >>= 1) {
        S += __shfl_xor_sync(0xFFFFFFFF, S, m);
        Q += __shfl_xor_sync(0xFFFFFFFF, Q, m);
    }
    if (lane == 0) {
        const float inv_cnt = 1.f / (float)(4 * OH * OW);
        float mean = S * inv_cnt;
        float var  = Q * inv_cnt - mean * mean;
        g_mean[wg] = mean;
        g_rsig[wg] = rsqrtf(var + 1e-5f);
    }
}

// ---------------------------------------------------------------------------
// Kernel 3: affine on pre-selected extreme, clamp. 4 px / thread (float4).
// ---------------------------------------------------------------------------
__global__ __launch_bounds__(256) void finalize_pool_kernel(
    const float* __restrict__ gnw,
    const float* __restrict__ gnb,
    const float* __restrict__ scale,
    float* __restrict__ out)
{
    const int total4 = (N_ * COUT * OPH * OPW) >> 2;
    int t4 = blockIdx.x * 256 + threadIdx.x;
    if (t4 >= total4) return;
    int idx = t4 << 2;

    float4 e = *(const float4*)(g_ext + idx);
    float r[4] = {e.x, e.y, e.z, e.w};
    float4 o;
    float* op = &o.x;

    #pragma unroll
    for (int i = 0; i < 4; ++i) {
        int id = idx + i;
        int t = id / (OPH * OPW);
        int c = t % COUT;
        int n = t / COUT;
        int gi = n * G_ + (c >> 2);
        float mean = g_mean[gi];
        float rsig = g_rsig[gi];
        float a = rsig * gnw[c] * scale[c];
        float b = (gnb[c] - mean * rsig * gnw[c]) * scale[c];
        op[i] = fminf(fmaxf(fmaf(r[i], a, b), 0.f), 1.f);
    }
    *(float4*)(out + idx) = o;
}

// ---------------------------------------------------------------------------
extern "C" void kernel_launch(void* const* d_in, const int* in_sizes, int n_in,
                              void* d_out, int out_size)
{
    const float* x     = (const float*)d_in[0];
    const float* cw    = (const float*)d_in[1];
    const float* cb    = (const float*)d_in[2];
    const float* gnw   = (const float*)d_in[3];
    const float* gnb   = (const float*)d_in[4];
    const float* scale = (const float*)d_in[5];
    float* out = (float*)d_out;

    static bool attr_set = false;
    if (!attr_set) {
        cudaFuncSetAttribute(conv_mma_kernel,
                             cudaFuncAttributeMaxDynamicSharedMemorySize, SMEM_TOTAL);
        attr_set = true;
    }

    bprep_kernel<<<6, 256>>>(cw, gnw, scale);

    dim3 grid(WB_ * 2, HB_, N_);
    conv_mma_kernel<<<grid, 256, SMEM_TOTAL>>>(x, cb);

    stats_reduce_kernel<<<(N_ * G_ * 32 + 255) / 256, 256>>>();

    const int total4 = (N_ * COUT * OPH * OPW) / 4;
    finalize_pool_kernel<<<(total4 + 255) / 256, 256>>>(gnw, gnb, scale, out);
}

// round 13
// speedup vs baseline: 1.3111x; 1.3111x over previous
#include <cuda_runtime.h>
#include <cuda_fp16.h>
#include <cstdint>
#include <cstddef>

#define N_    128
#define CIN   8
#define HIN   128
#define WIN   128
#define COUT  64
#define OH    126
#define OW    126
#define G_    16
#define OPH   31
#define OPW   31

#define HB_   16
#define WB_   4
#define NTILES (N_ * HB_ * WB_)

// ---- smem layout (bytes) ----
// resident: sB2 [0,10240) — NOT aliased (must survive both tiles)
// phase 1:  sX  [10240,23200)  (9 ic planes x 10 x 36, plane 8 zeros)
// phase 2:  sO  [10240,86016)  (256 px x 74 floats) — sX aliases sO's front
#define OFF_B2   0
#define OFF_X    10240
#define OFF_OUT  10240
#define OFF_CB   86016
#define OFF_RED  86272
#define OFF_SG   88320
#define SMEM_TOTAL 88576

#define SO 74    // s_out px stride

// ---- device scratch ----
// B pairs: [oc][kk(5)][r4(4)] uint2 = (half2(k0,k0+1), half2(k0+8,k0+9)), k0=16kk+2r4
__device__ uint2 g_B2h[64 * 20];
__device__ float g_sgn[64];
__device__ float g_ext[(size_t)N_ * COUT * OPH * OPW];
__device__ float g_ps[NTILES * G_];
__device__ float g_pq[NTILES * G_];
__device__ float g_mean[N_ * G_];
__device__ float g_rsig[N_ * G_];

__device__ __forceinline__ uint32_t pack_h2(float lo, float hi) {
    uint32_t r;
    asm("cvt.rn.f16x2.f32 %0, %1, %2;" : "=r"(r) : "f"(hi), "f"(lo));
    return r;
}

__device__ __forceinline__ void mma16(float* c, const uint32_t* a, uint32_t b0, uint32_t b1) {
    asm volatile(
        "mma.sync.aligned.m16n8k16.row.col.f32.f16.f16.f32 "
        "{%0,%1,%2,%3}, {%4,%5,%6,%7}, {%8,%9}, {%0,%1,%2,%3};"
        : "+f"(c[0]), "+f"(c[1]), "+f"(c[2]), "+f"(c[3])
        : "r"(a[0]), "r"(a[1]), "r"(a[2]), "r"(a[3]), "r"(b0), "r"(b1));
}

// k (< 80) -> sX offset ic*360 + kh*36 + kw   (sX layout [ic(9)][10][36])
__device__ __forceinline__ int koff(int k) {
    int ic = (k * 57) >> 9;
    int r  = k - 9 * ic;
    int kh = (r * 11) >> 5;
    int kw = r - 3 * kh;
    return ic * 360 + kh * 36 + kw;
}

// ---------------------------------------------------------------------------
// Kernel 0: weights -> fp16 pairs keyed [oc][kk][r4]; sign of a per oc.
// ---------------------------------------------------------------------------
__global__ void bprep_kernel(const float* __restrict__ cw,
                             const float* __restrict__ gnw,
                             const float* __restrict__ scale)
{
    int e = blockIdx.x * blockDim.x + threadIdx.x;
    if (e < 64) g_sgn[e] = (gnw[e] * scale[e] > 0.f) ? 1.f : -1.f;
    if (e >= 64 * 20) return;
    int oc = e / 20, rem = e - (e / 20) * 20;
    int kk = rem >> 2, r4 = rem & 3;
    int k0 = 16 * kk + 2 * r4;

    float w[4];
    #pragma unroll
    for (int i = 0; i < 4; ++i) {
        int k = k0 + ((i >> 1) << 3) + (i & 1);
        float v = 0.f;
        if (k < 72) {
            int ic = k / 9, r = k % 9;
            v = cw[((oc * 8 + ic) * 3 + r / 3) * 3 + (r % 3)];
        }
        w[i] = v;
    }
    __half2 p0 = __floats2half2_rn(w[0], w[1]);
    __half2 p1 = __floats2half2_rn(w[2], w[3]);
    uint2 out;
    out.x = *(uint32_t*)&p0;
    out.y = *(uint32_t*)&p1;
    g_B2h[e] = out;
}

// ---------------------------------------------------------------------------
// Kernel 1: implicit-GEMM conv (mma.sync fp16, f32 accum) + fused pool
// extreme + per-group partials. TWO h-tiles per block; tile 1's input is
// prefetched into registers during tile 0's compute phase.
// 256 threads, grid (wb, hb2, n) with hb = 2*hb2 + it.
// ---------------------------------------------------------------------------
__global__ __launch_bounds__(256, 2)
void conv_mma_kernel(const float* __restrict__ x, const float* __restrict__ cb)
{
    extern __shared__ char smem[];
    uint2*  sB2 = (uint2*)(smem + OFF_B2);    // [oc][kk][r4], stride 20/oc (resident)
    float*  sX  = (float*)(smem + OFF_X);     // [9][10][36], plane 8 zeroed
    float*  sO  = (float*)(smem + OFF_OUT);   // [256][SO]
    float*  sCb = (float*)(smem + OFF_CB);
    float*  sRd = (float*)(smem + OFF_RED);
    float*  sSg = (float*)(smem + OFF_SG);

    const int tid  = threadIdx.x;
    const int wid  = tid >> 5;
    const int lane = tid & 31;
    const int wb = blockIdx.x, hb2 = blockIdx.y, n = blockIdx.z;
    const int w0 = wb * 32;

    const int q  = lane >> 2;
    const int r4 = lane & 3;

    // copy packed weights once per block (640 float4) — survives both tiles
    {
        const float4* src = (const float4*)g_B2h;
        float4* dst = (float4*)sB2;
        #pragma unroll 3
        for (int i = tid; i < 640; i += 256) dst[i] = src[i];
    }
    if (tid < 64) { sCb[tid] = cb[tid]; sSg[tid] = g_sgn[tid]; }

    // per-thread staging coordinates (4 chunks of 256 cover 810 float4 slots)
    int s_ic[4], s_hr[4], s_c4[4];
    #pragma unroll
    for (int i = 0; i < 4; ++i) {
        int idx = tid + (i << 8);
        s_ic[i] = idx / 90;
        int rem = idx - s_ic[i] * 90;
        s_hr[i] = rem / 9;
        s_c4[i] = rem - s_hr[i] * 9;
    }

    // ---- stage tile 0 ----
    {
        const int h0 = (hb2 * 2) * 8;
        #pragma unroll
        for (int i = 0; i < 4; ++i) {
            int idx = tid + (i << 8);
            if (idx >= 810) break;
            int ic = s_ic[i], h = h0 + s_hr[i], gw = w0 + s_c4[i] * 4;
            float4 v = make_float4(0.f, 0.f, 0.f, 0.f);
            if (ic < CIN && h < HIN) {
                const float* rp = x + (((size_t)n * CIN + ic) * HIN + h) * WIN;
                if (gw + 3 < WIN) v = *(const float4*)(rp + gw);
                else {
                    if (gw + 0 < WIN) v.x = rp[gw + 0];
                    if (gw + 1 < WIN) v.y = rp[gw + 1];
                    if (gw + 2 < WIN) v.z = rp[gw + 2];
                }
            }
            *(float4*)(sX + (ic * 10 + s_hr[i]) * 36 + s_c4[i] * 4) = v;
        }
    }
    __syncthreads();

    const int P = wid * 36 + 4 * q;
    float4 pf[4];   // register prefetch buffer for tile 1

    #pragma unroll
    for (int it = 0; it < 2; ++it) {
        const int hb = hb2 * 2 + it;
        const int h0 = hb * 8;

        // prefetch tile 1 input into registers (overlaps tile 0 compute)
        if (it == 0) {
            const int h1 = (hb2 * 2 + 1) * 8;
            #pragma unroll
            for (int i = 0; i < 4; ++i) {
                int idx = tid + (i << 8);
                float4 v = make_float4(0.f, 0.f, 0.f, 0.f);
                int ic = s_ic[i], h = h1 + s_hr[i], gw = w0 + s_c4[i] * 4;
                if (idx < 810 && ic < CIN && h < HIN) {
                    const float* rp = x + (((size_t)n * CIN + ic) * HIN + h) * WIN;
                    if (gw + 3 < WIN) v = *(const float4*)(rp + gw);
                    else {
                        if (gw + 0 < WIN) v.x = rp[gw + 0];
                        if (gw + 1 < WIN) v.y = rp[gw + 1];
                        if (gw + 2 < WIN) v.z = rp[gw + 2];
                    }
                }
                pf[i] = v;
            }
        }

        // ---- MMA mainloop: 5 k16-steps (K padded 72 -> 80) ----
        float acc[2][8][4];
        #pragma unroll
        for (int t = 0; t < 2; ++t)
            #pragma unroll
            for (int j = 0; j < 8; ++j)
                #pragma unroll
                for (int u = 0; u < 4; ++u) acc[t][j][u] = 0.f;

        #pragma unroll
        for (int kk = 0; kk < 5; ++kk) {
            const int k0 = 16 * kk + 2 * r4;
            const float* p00 = sX + koff(k0)     + P;
            const float* p01 = sX + koff(k0 + 1) + P;
            const float* p10 = sX + koff(k0 + 8) + P;
            const float* p11 = sX + koff(k0 + 9) + P;

            uint32_t a[2][4];
            #pragma unroll
            for (int t = 0; t < 2; ++t) {
                const int c = 2 * t;
                a[t][0] = pack_h2(p00[c],     p01[c]);
                a[t][1] = pack_h2(p00[c + 1], p01[c + 1]);
                a[t][2] = pack_h2(p10[c],     p11[c]);
                a[t][3] = pack_h2(p10[c + 1], p11[c + 1]);
            }
            const uint2* bp = sB2 + q * 20 + kk * 4 + r4;
            #pragma unroll
            for (int j = 0; j < 8; ++j) {
                uint2 bv = bp[j * 160];
                mma16(acc[0][j], a[0], bv.x, bv.y);
                mma16(acc[1][j], a[1], bv.x, bv.y);
            }
        }
        __syncthreads();   // sX dead; region becomes part of sO

        // ---- epilogue: +bias, zero invalid, paired STS.64 -> sO[px][oc] ----
        const bool hok = (h0 + wid) < OH;
        #pragma unroll
        for (int t = 0; t < 2; ++t) {
            const int ww0 = 4 * q + 2 * t;
            const int px  = (wid << 5) + ww0;
            const bool v0 = hok && (w0 + ww0 < OW);
            const bool v1 = hok && (w0 + ww0 + 1 < OW);
            #pragma unroll
            for (int j = 0; j < 8; ++j) {
                const int oc = (j << 3) + (r4 << 1);
                float2 bc = *(float2*)(sCb + oc);
                float2 e0, e1;
                e0.x = v0 ? acc[t][j][0] + bc.x : 0.f;
                e0.y = v0 ? acc[t][j][1] + bc.y : 0.f;
                e1.x = v1 ? acc[t][j][2] + bc.x : 0.f;
                e1.y = v1 ? acc[t][j][3] + bc.y : 0.f;
                *(float2*)(sO + px * SO + oc)       = e0;
                *(float2*)(sO + (px + 1) * SO + oc) = e1;
            }
        }
        __syncthreads();

        // ---- stats: column scan, 4 partials per oc, fixed order ----
        {
            const int oc = tid & 63, part = tid >> 6;
            const float* p = sO + part * 64 * SO + oc;
            float s = 0.f, qq = 0.f;
            #pragma unroll 8
            for (int i = 0; i < 64; ++i) {
                float v = p[i * SO];
                s += v; qq = fmaf(v, v, qq);
            }
            sRd[tid] = s; sRd[256 + tid] = qq;
        }
        __syncthreads();

        const int tile = (n * HB_ + hb) * WB_ + wb;
        if (tid < 16) {
            float S = 0.f, Q = 0.f;
            #pragma unroll
            for (int part = 0; part < 4; ++part)
                #pragma unroll
                for (int c2 = 0; c2 < 4; ++c2) {
                    S += sRd[part * 64 + tid * 4 + c2];
                    Q += sRd[256 + part * 64 + tid * 4 + c2];
                }
            g_ps[tile * G_ + tid] = S;
            g_pq[tile * G_ + tid] = Q;
        }

        // ---- pool: sign-relevant extreme only ----
        #pragma unroll
        for (int i = 0; i < 4; ++i) {
            const int task = tid + (i << 8);
            const int oc = task & 63, j = (task >> 6) & 7, prl = task >> 9;
            const int pw = wb * 8 + j, pr = hb * 2 + prl;
            if (pw < OPW && pr < OPH) {
                float mx = -3.4e38f, mn = 3.4e38f;
                #pragma unroll
                for (int a2 = 0; a2 < 4; ++a2)
                    #pragma unroll
                    for (int b2 = 0; b2 < 4; ++b2) {
                        float v = sO[((prl * 4 + a2) * 32 + j * 4 + b2) * SO + oc];
                        mx = fmaxf(mx, v); mn = fminf(mn, v);
                    }
                size_t o = ((size_t)(n * COUT + oc) * OPH + pr) * OPW + pw;
                g_ext[o] = (sSg[oc] > 0.f) ? mx : mn;
            }
        }

        // ---- commit prefetched tile 1 into sX (after sO reads complete) ----
        if (it == 0) {
            __syncthreads();   // pool/stats reads of sO done; sX region reusable
            #pragma unroll
            for (int i = 0; i < 4; ++i) {
                int idx = tid + (i << 8);
                if (idx < 810)
                    *(float4*)(sX + (s_ic[i] * 10 + s_hr[i]) * 36 + s_c4[i] * 4) = pf[i];
            }
            __syncthreads();
        }
    }
}

// ---------------------------------------------------------------------------
// Kernel 2: reduce per-tile partials -> mean, rsig. One warp per (n,g),
// fixed shuffle tree (deterministic).
// ---------------------------------------------------------------------------
__global__ __launch_bounds__(256) void stats_reduce_kernel()
{
    const int wg   = (blockIdx.x * 256 + threadIdx.x) >> 5;
    const int lane = threadIdx.x & 31;
    if (wg >= N_ * G_) return;
    const int n = wg / G_, g = wg - n * G_;

    const int base = n * HB_ * WB_;   // 64 tiles per n
    float S = g_ps[(base + lane) * G_ + g] + g_ps[(base + 32 + lane) * G_ + g];
    float Q = g_pq[(base + lane) * G_ + g] + g_pq[(base + 32 + lane) * G_ + g];
    #pragma unroll
    for (int m = 16; m > 0; m >>= 1) {
        S += __shfl_xor_sync(0xFFFFFFFF, S, m);
        Q += __shfl_xor_sync(0xFFFFFFFF, Q, m);
    }
    if (lane == 0) {
        const float inv_cnt = 1.f / (float)(4 * OH * OW);
        float mean = S * inv_cnt;
        float var  = Q * inv_cnt - mean * mean;
        g_mean[wg] = mean;
        g_rsig[wg] = rsqrtf(var + 1e-5f);
    }
}

// ---------------------------------------------------------------------------
// Kernel 3: affine on pre-selected extreme, clamp. 4 px / thread (float4).
// ---------------------------------------------------------------------------
__global__ __launch_bounds__(256) void finalize_pool_kernel(
    const float* __restrict__ gnw,
    const float* __restrict__ gnb,
    const float* __restrict__ scale,
    float* __restrict__ out)
{
    const int total4 = (N_ * COUT * OPH * OPW) >> 2;
    int t4 = blockIdx.x * 256 + threadIdx.x;
    if (t4 >= total4) return;
    int idx = t4 << 2;

    float4 e = *(const float4*)(g_ext + idx);
    float r[4] = {e.x, e.y, e.z, e.w};
    float4 o;
    float* op = &o.x;

    #pragma unroll
    for (int i = 0; i < 4; ++i) {
        int id = idx + i;
        int t = id / (OPH * OPW);
        int c = t % COUT;
        int n = t / COUT;
        int gi = n * G_ + (c >> 2);
        float mean = g_mean[gi];
        float rsig = g_rsig[gi];
        float a = rsig * gnw[c] * scale[c];
        float b = (gnb[c] - mean * rsig * gnw[c]) * scale[c];
        op[i] = fminf(fmaxf(fmaf(r[i], a, b), 0.f), 1.f);
    }
    *(float4*)(out + idx) = o;
}

// ---------------------------------------------------------------------------
extern "C" void kernel_launch(void* const* d_in, const int* in_sizes, int n_in,
                              void* d_out, int out_size)
{
    const float* x     = (const float*)d_in[0];
    const float* cw    = (const float*)d_in[1];
    const float* cb    = (const float*)d_in[2];
    const float* gnw   = (const float*)d_in[3];
    const float* gnb   = (const float*)d_in[4];
    const float* scale = (const float*)d_in[5];
    float* out = (float*)d_out;

    static bool attr_set = false;
    if (!attr_set) {
        cudaFuncSetAttribute(conv_mma_kernel,
                             cudaFuncAttributeMaxDynamicSharedMemorySize, SMEM_TOTAL);
        attr_set = true;
    }

    bprep_kernel<<<6, 256>>>(cw, gnw, scale);

    dim3 grid(WB_, HB_ / 2, N_);
    conv_mma_kernel<<<grid, 256, SMEM_TOTAL>>>(x, cb);

    stats_reduce_kernel<<<(N_ * G_ * 32 + 255) / 256, 256>>>();

    const int total4 = (N_ * COUT * OPH * OPW) / 4;
    finalize_pool_kernel<<<(total4 + 255) / 256, 256>>>(gnw, gnb, scale, out);
}